// round 1
// baseline (speedup 1.0000x reference)
#include <cuda_runtime.h>
#include <math.h>

#define BQ 2048
#define NQ 128
#define HQ 512
#define TAUC 0.05f
#define BT 8
#define NITER 14   // Richardson iterations (even)

// scratch (allocation-free rule: __device__ globals)
__device__ float g_d[BQ * NQ];
__device__ float g_u[BQ * NQ];

// ---------------------------------------------------------------------------
// Kernel A: fused GEMM (hidden @ {Wq,Wp,Wo}^T + bias) + activations.
// Produces d = p^2/omega + 1e-6 and u = t/d with t = (p/omega)*q.
// CTA: 8 batches x 128 outputs x 3 weights. 256 threads, 4 batches/thread.
// ---------------------------------------------------------------------------
__global__ void __launch_bounds__(256) gemm_act_kernel(
    const float* __restrict__ hidden,
    const float* __restrict__ Wq, const float* __restrict__ Wp,
    const float* __restrict__ Wo,
    const float* __restrict__ bq, const float* __restrict__ bp,
    const float* __restrict__ bo)
{
    __shared__ float4 Ht[BT * HQ / 4];   // 8x512 floats = 16 KB
    const int tid = threadIdx.x;
    const int b0 = blockIdx.x * BT;

    const float4* hg = (const float4*)(hidden + (size_t)b0 * HQ);
#pragma unroll
    for (int i = 0; i < (BT * HQ / 4) / 256; i++)
        Ht[tid + 256 * i] = hg[tid + 256 * i];
    __syncthreads();

    const int n = tid & 127;
    const int half = tid >> 7;

    const float4* wq4 = (const float4*)(Wq + (size_t)n * HQ);
    const float4* wp4 = (const float4*)(Wp + (size_t)n * HQ);
    const float4* wo4 = (const float4*)(Wo + (size_t)n * HQ);

    float aq[4] = {0.f, 0.f, 0.f, 0.f};
    float ap[4] = {0.f, 0.f, 0.f, 0.f};
    float ao[4] = {0.f, 0.f, 0.f, 0.f};

    const float4* hrow0 = &Ht[(half * 4 + 0) * (HQ / 4)];
    const float4* hrow1 = &Ht[(half * 4 + 1) * (HQ / 4)];
    const float4* hrow2 = &Ht[(half * 4 + 2) * (HQ / 4)];
    const float4* hrow3 = &Ht[(half * 4 + 3) * (HQ / 4)];

#pragma unroll 4
    for (int k4 = 0; k4 < HQ / 4; k4++) {
        const float4 wq = wq4[k4];
        const float4 wp = wp4[k4];
        const float4 wo = wo4[k4];
        float4 h;
#define DO_ROW(m, HR)                                                          \
        h = HR[k4];                                                            \
        aq[m] = fmaf(h.x, wq.x, fmaf(h.y, wq.y, fmaf(h.z, wq.z, fmaf(h.w, wq.w, aq[m])))); \
        ap[m] = fmaf(h.x, wp.x, fmaf(h.y, wp.y, fmaf(h.z, wp.z, fmaf(h.w, wp.w, ap[m])))); \
        ao[m] = fmaf(h.x, wo.x, fmaf(h.y, wo.y, fmaf(h.z, wo.z, fmaf(h.w, wo.w, ao[m]))));
        DO_ROW(0, hrow0)
        DO_ROW(1, hrow1)
        DO_ROW(2, hrow2)
        DO_ROW(3, hrow3)
#undef DO_ROW
    }

    const float bqv = bq[n], bpv = bp[n], bov = bo[n];
#pragma unroll
    for (int m = 0; m < 4; m++) {
        const int b = b0 + half * 4 + m;
        const float lq = aq[m] + bqv;
        const float lp = ap[m] + bpv;
        const float lo = ao[m] + bov;
        const float q = tanhf(lq);
        const float p = 1.0f / (1.0f + expf(-lp));
        // stable softplus + 1e-6 (matches jax.nn.softplus)
        const float om = fmaxf(lo, 0.0f) + log1pf(expf(-fabsf(lo))) + 1e-6f;
        const float d = p * p / om + 1e-6f;
        const float t = p * q / om;
        g_d[b * NQ + n] = d;
        g_u[b * NQ + n] = t / d;
    }
}

// ---------------------------------------------------------------------------
// Kernel B: per-batch solve of (I + M D) mu = pi + M t via Richardson.
// E = M*diag(d) lives in registers: thread (r = tid>>1, h = tid&1) owns
// E[r][h*64 .. h*64+63]. M t computed as E * (t./d). x in smem (broadcast).
// ---------------------------------------------------------------------------
__device__ __forceinline__ float matvec_half(const float* E, const float4* x4, int h)
{
    float a0 = 0.f, a1 = 0.f;
#pragma unroll
    for (int k = 0; k < 16; k++) {
        const float4 xv = x4[h * 16 + k];
        a0 = fmaf(E[4 * k + 0], xv.x, a0);
        a1 = fmaf(E[4 * k + 1], xv.y, a1);
        a0 = fmaf(E[4 * k + 2], xv.z, a0);
        a1 = fmaf(E[4 * k + 3], xv.w, a1);
    }
    float s = a0 + a1;
    s += __shfl_xor_sync(0xffffffffu, s, 1);   // combine the two halves of row r
    return s;
}

__global__ void __launch_bounds__(256, 2) solve_kernel(
    const float* __restrict__ pi,
    const float* __restrict__ sigma,
    float* __restrict__ out)
{
    __shared__ __align__(16) float sm_d[NQ];
    __shared__ __align__(16) float sm_u[NQ];
    __shared__ __align__(16) float sm_a[NQ];
    __shared__ __align__(16) float xA[NQ];
    __shared__ __align__(16) float xB[NQ];

    const int tid = threadIdx.x;
    const int b = blockIdx.x;
    const int r = tid >> 1;
    const int h = tid & 1;

    if (tid < NQ) {
        sm_d[tid] = g_d[b * NQ + tid];
        sm_u[tid] = g_u[b * NQ + tid];
    }
    __syncthreads();

    // Build E = (TAU*sigma + 1e-6 I) * diag(d) into registers.
    float E[64];
    const float4* sg = (const float4*)(sigma + (size_t)b * NQ * NQ) + tid * 16;
    const float4* d4 = (const float4*)sm_d;
#pragma unroll
    for (int k = 0; k < 16; k++) {
        const float4 s = sg[k];
        const float4 dv = d4[h * 16 + k];
        const int j = h * 64 + 4 * k;
        E[4 * k + 0] = (TAUC * s.x + ((r == j + 0) ? 1e-6f : 0.f)) * dv.x;
        E[4 * k + 1] = (TAUC * s.y + ((r == j + 1) ? 1e-6f : 0.f)) * dv.y;
        E[4 * k + 2] = (TAUC * s.z + ((r == j + 2) ? 1e-6f : 0.f)) * dv.z;
        E[4 * k + 3] = (TAUC * s.w + ((r == j + 3) ? 1e-6f : 0.f)) * dv.w;
    }

    // a = pi + M t = pi + E * (t./d);  x0 = a
    {
        const float s = matvec_half(E, (const float4*)sm_u, h);
        if (h == 0) {
            const float a = pi[b * NQ + r] + s;
            sm_a[r] = a;
            xA[r] = a;
        }
    }
    __syncthreads();

    // Richardson: x <- a - E x   (converges to (I + E)^{-1} a, rho ~ 0.2)
#pragma unroll 1
    for (int it = 0; it < NITER / 2; it++) {
        float s = matvec_half(E, (const float4*)xA, h);
        if (h == 0) xB[r] = sm_a[r] - s;
        __syncthreads();
        s = matvec_half(E, (const float4*)xB, h);
        if (h == 0) xA[r] = sm_a[r] - s;
        __syncthreads();
    }

    if (tid < NQ) out[b * NQ + tid] = xA[tid];
}

// ---------------------------------------------------------------------------
extern "C" void kernel_launch(void* const* d_in, const int* in_sizes, int n_in,
                              void* d_out, int out_size)
{
    const float* hidden = (const float*)d_in[0];
    const float* pi     = (const float*)d_in[1];
    const float* sigma  = (const float*)d_in[2];
    const float* Wq     = (const float*)d_in[3];
    const float* bq     = (const float*)d_in[4];
    const float* Wp     = (const float*)d_in[5];
    const float* bp     = (const float*)d_in[6];
    const float* Wo     = (const float*)d_in[7];
    const float* bo     = (const float*)d_in[8];

    gemm_act_kernel<<<BQ / BT, 256>>>(hidden, Wq, Wp, Wo, bq, bp, bo);
    solve_kernel<<<BQ, 256>>>(pi, sigma, (float*)d_out);
}